// round 14
// baseline (speedup 1.0000x reference)
#include <cuda_runtime.h>
#include <cuda_bf16.h>
#include <math.h>
#include <stdint.h>

// ---------------------------------------------------------------- constants
#define Bb   4
#define Tt   2048
#define Hh   1024
#define NHh  16
#define HDh  64
#define BT   (Bb*Tt)          // 8192 tokens
#define BTH  (BT*Hh)          // 8388608
#define DECAYC (-0.6065306597126334f)
#define GN_EPS (HDh*1e-5f)    // 6.4e-4

// ---------------------------------------------------------------- scratch (aliased by liveness)
__device__ __align__(128) float g_xr[BTH], g_xw[BTH], g_xk[BTH], g_xv[BTH], g_xa[BTH], g_xg[BTH];
__device__ __align__(128) float g_r[BTH], g_k[BTH], g_v0[BTH];
__device__ __align__(128) float g_hw[BT*64], g_hv[BT*64], g_ha[BT*64], g_hg[BT*160];
__device__ __align__(128) float g_wl[BTH], g_vl[BTH], g_al[BTH], g_gl[BTH];

// weight split scratch (bf16 hi/lo planes, per-weight: hi at off, lo at off+size)
#define SZ_BIG 1048576
#define SZ_LORA 65536
#define SZ_G  163840
#define OFF_WR 0
#define OFF_WK 2097152
#define OFF_WV 4194304
#define OFF_WO 6291456
#define OFF_wA 8388608
#define OFF_vA 8519680
#define OFF_aA 8650752
#define OFF_gA 8781824
#define OFF_wB 9109504
#define OFF_vB 9240576
#define OFF_aB 9371648
#define OFF_gB 9502720
#define WSPLIT_TOTAL 9830400
__device__ __align__(128) __nv_bfloat16 g_wsplit[WSPLIT_TOTAL];

#define g_rH  g_xr
#define g_wHe g_xw
#define g_kH  g_xk
#define g_vH  g_xv
#define g_aH  g_xa
#define g_bH  g_xg
#define g_y   g_vl
#define g_oH  g_r     // dead after prep_scan; scan writes full o here

// ---------------------------------------------------------------- helpers
__device__ __forceinline__ uint32_t smem_u32(const void* p) {
    uint32_t a;
    asm("{ .reg .u64 t; cvta.to.shared.u64 t, %1; cvt.u32.u64 %0, t; }" : "=r"(a) : "l"(p));
    return a;
}
__device__ __forceinline__ float warp_sum(float v) {
    #pragma unroll
    for (int o = 16; o > 0; o >>= 1) v += __shfl_xor_sync(0xffffffffu, v, o);
    return v;
}
__device__ __forceinline__ void cvt_split2(float a, float b, uint32_t& hi, uint32_t& lo) {
    __nv_bfloat162 h = __float22bfloat162_rn(make_float2(a, b));
    float2 hf = __bfloat1622float2(h);
    __nv_bfloat162 l = __float22bfloat162_rn(make_float2(a - hf.x, b - hf.y));
    hi = *(uint32_t*)&h;
    lo = *(uint32_t*)&l;
}

#define CP_A16(dst, src)      asm volatile("cp.async.cg.shared.global [%0], [%1], 16;" :: "r"(dst), "l"(src) : "memory")
#define CP_A16Z(dst, src, sz) asm volatile("cp.async.cg.shared.global [%0], [%1], 16, %2;" :: "r"(dst), "l"(src), "r"(sz) : "memory")
#define CP_COMMIT()           asm volatile("cp.async.commit_group;" ::: "memory")
#define CP_WAIT(n)            asm volatile("cp.async.wait_group %0;" :: "n"(n) : "memory")

#define LDSM_X4(r, addr) \
    asm volatile("ldmatrix.sync.aligned.m8n8.x4.shared.b16 {%0,%1,%2,%3}, [%4];" \
        : "=r"((r)[0]),"=r"((r)[1]),"=r"((r)[2]),"=r"((r)[3]) : "r"(addr))
#define LDSM_X4_T(r, addr) \
    asm volatile("ldmatrix.sync.aligned.m8n8.x4.trans.shared.b16 {%0,%1,%2,%3}, [%4];" \
        : "=r"((r)[0]),"=r"((r)[1]),"=r"((r)[2]),"=r"((r)[3]) : "r"(addr))

#define MMA_BF16(d, a, b) \
    asm volatile("mma.sync.aligned.m16n8k16.row.col.f32.bf16.bf16.f32 " \
        "{%0,%1,%2,%3}, {%4,%5,%6,%7}, {%8,%9}, {%0,%1,%2,%3};" \
        : "+f"((d)[0]),"+f"((d)[1]),"+f"((d)[2]),"+f"((d)[3]) \
        : "r"((a)[0]),"r"((a)[1]),"r"((a)[2]),"r"((a)[3]), "r"((b)[0]),"r"((b)[1]))

struct GemmZ {
    const __nv_bfloat16 *Ahi, *Alo, *Bhi, *Blo;
    float* C;
    __nv_bfloat16 *Chi, *Clo;
    const float* bias;
    int act;            // 0 none, 1 tanh, 2 sigmoid
    int N;              // per-z N
    int K;              // per-z K
};
struct GemmBatch { GemmZ z[4]; };

__device__ __forceinline__ float ep_act(float t, int act) {
    if (act == 1) return tanhf(t);
    if (act == 2) return 1.f / (1.f + __expf(-t));
    return t;
}

// ---------------------------------------------------------------- TN=128 GEMM body (proven)
#define G_STAGE 36864u
#define G_SMEM  (2*36864 + 1024)

__device__ __forceinline__ void gemm128_body(const GemmZ& zz, int m0, int n0, char* dsm) {
    uint32_t sb = (smem_u32(dsm) + 1023u) & ~1023u;
    int N = zz.N, K = zz.K;
    int tid = threadIdx.x;
    int wid = tid >> 5, lane = tid & 31;
    int wm = wid >> 2, wn = wid & 3;
    int nt = K >> 5;

    auto issue = [&](int it) {
        uint32_t base = sb + (uint32_t)(it & 1) * G_STAGE;
        int k0 = it << 5;
        #pragma unroll
        for (int s = 0; s < 2; ++s) {
            int ca = tid + s * 256;
            int row = ca >> 2, cc = ca & 3;
            size_t so = (size_t)(m0 + row) * K + k0 + cc * 8;
            uint32_t da = base + (uint32_t)(row * 80 + cc * 16);
            CP_A16(da, zz.Ahi + so);
            CP_A16(da + 10240u, zz.Alo + so);
        }
        #pragma unroll
        for (int s = 0; s < 2; ++s) {
            int cb = tid + s * 256;
            int kk = cb >> 4, j = cb & 15;
            int gn = n0 + j * 8;
            uint32_t sz = (gn < N) ? 16u : 0u;
            size_t so = (size_t)(k0 + kk) * N + ((gn < N) ? gn : 0);
            uint32_t db = base + 20480u + (uint32_t)(kk * 256 + ((j ^ (kk & 7)) * 16));
            CP_A16Z(db, zz.Bhi + so, sz);
            CP_A16Z(db + 8192u, zz.Blo + so, sz);
        }
        CP_COMMIT();
    };

    float acc[4][4][4];
    #pragma unroll
    for (int i = 0; i < 4; i++)
        #pragma unroll
        for (int j = 0; j < 4; j++)
            #pragma unroll
            for (int q = 0; q < 4; q++) acc[i][j][q] = 0.f;

    issue(0);
    for (int it = 0; it < nt; ++it) {
        if (it + 1 < nt) { issue(it + 1); CP_WAIT(1); }
        else             { CP_WAIT(0); }
        __syncthreads();
        uint32_t base = sb + (uint32_t)(it & 1) * G_STAGE;

        #pragma unroll
        for (int h = 0; h < 2; ++h) {
            uint32_t a_hi[16], b_hi[8], tmp[16];
            int lrow = lane & 15, lchk = lane >> 4;
            uint32_t ad[4];
            #pragma unroll
            for (int mf = 0; mf < 4; ++mf) {
                ad[mf] = base + (uint32_t)((wm * 64 + mf * 16 + lrow) * 80 + (h * 2 + lchk) * 16);
                LDSM_X4(&a_hi[mf * 4], ad[mf]);
            }
            int krow = h * 16 + (lane & 15);
            uint32_t bd[2];
            #pragma unroll
            for (int pr = 0; pr < 2; ++pr) {
                int nabs = wn * 32 + pr * 16 + (lane >> 4) * 8;
                int clog = nabs >> 3;
                bd[pr] = base + 20480u + (uint32_t)(krow * 256 + ((clog ^ (krow & 7)) * 16));
                LDSM_X4_T(&b_hi[pr * 4], bd[pr]);
            }
            #pragma unroll
            for (int mf = 0; mf < 4; ++mf)
                #pragma unroll
                for (int nf = 0; nf < 4; ++nf)
                    MMA_BF16(acc[mf][nf], &a_hi[mf * 4], (&b_hi[(nf >> 1) * 4 + (nf & 1) * 2]));
            #pragma unroll
            for (int mf = 0; mf < 4; ++mf) LDSM_X4(&tmp[mf * 4], ad[mf] + 10240u);
            #pragma unroll
            for (int mf = 0; mf < 4; ++mf)
                #pragma unroll
                for (int nf = 0; nf < 4; ++nf)
                    MMA_BF16(acc[mf][nf], &tmp[mf * 4], (&b_hi[(nf >> 1) * 4 + (nf & 1) * 2]));
            #pragma unroll
            for (int pr = 0; pr < 2; ++pr) LDSM_X4_T(&b_hi[pr * 4], bd[pr] + 8192u);
            #pragma unroll
            for (int mf = 0; mf < 4; ++mf)
                #pragma unroll
                for (int nf = 0; nf < 4; ++nf)
                    MMA_BF16(acc[mf][nf], &a_hi[mf * 4], (&b_hi[(nf >> 1) * 4 + (nf & 1) * 2]));
        }
        __syncthreads();
    }

    int rbase = lane >> 2;
    int cbase = (lane & 3) * 2;
    #pragma unroll
    for (int mf = 0; mf < 4; ++mf) {
        #pragma unroll
        for (int nf = 0; nf < 4; ++nf) {
            int col = n0 + wn * 32 + nf * 8 + cbase;
            if (col >= N) continue;
            float b0 = 0.f, b1 = 0.f;
            if (zz.bias) { b0 = zz.bias[col]; b1 = zz.bias[col + 1]; }
            #pragma unroll
            for (int half = 0; half < 2; ++half) {
                int row = m0 + wm * 64 + mf * 16 + rbase + half * 8;
                float t0 = ep_act(acc[mf][nf][half * 2 + 0] + b0, zz.act);
                float t1 = ep_act(acc[mf][nf][half * 2 + 1] + b1, zz.act);
                if (!zz.Chi) {
                    *(float2*)(zz.C + (size_t)row * N + col) = make_float2(t0, t1);
                } else {
                    uint32_t hw, lw;
                    cvt_split2(t0, t1, hw, lw);
                    *(uint32_t*)(zz.Chi + (size_t)row * N + col) = hw;
                    *(uint32_t*)(zz.Clo + (size_t)row * N + col) = lw;
                }
            }
        }
    }
}

__global__ __launch_bounds__(256, 2)
void gemm_mma(GemmBatch gb, int M) {
    extern __shared__ char dsm[];
    GemmZ zz = gb.z[blockIdx.z];
    gemm128_body(zz, blockIdx.y * 128, blockIdx.x * 128, dsm);
}

// ---------------------------------------------------------------- TN=64 GEMM body, 3-stage ring (tail-fixed)
#define N64_STAGE 28672u
#define N64_SMEM  (3*28672 + 1024)

__device__ __forceinline__ void gemm64_body(const GemmZ& zz, int m0, int n0, char* dsm) {
    uint32_t sb = (smem_u32(dsm) + 1023u) & ~1023u;
    int N = zz.N, K = zz.K;
    if (n0 >= N) return;                 // uniform per-block

    int tid = threadIdx.x;
    int wid = tid >> 5, lane = tid & 31;
    int wm = wid >> 2, wn = wid & 3;
    int nt = K >> 5;

    auto issue = [&](int it) {
        uint32_t base = sb + (uint32_t)(it % 3) * N64_STAGE;
        int k0 = it << 5;
        #pragma unroll
        for (int s = 0; s < 2; ++s) {
            int ca = tid + s * 256;
            int row = ca >> 2, cc = ca & 3;
            size_t so = (size_t)(m0 + row) * K + k0 + cc * 8;
            uint32_t da = base + (uint32_t)(row * 80 + cc * 16);
            CP_A16(da, zz.Ahi + so);
            CP_A16(da + 10240u, zz.Alo + so);
        }
        {
            int kk = tid >> 3, j = tid & 7;
            int gn = n0 + j * 8;
            uint32_t sz = (gn < N) ? 16u : 0u;
            size_t so = (size_t)(k0 + kk) * N + ((gn < N) ? gn : 0);
            uint32_t db = base + 20480u + (uint32_t)(kk * 128 + ((j ^ (kk & 7)) * 16));
            CP_A16Z(db, zz.Bhi + so, sz);
            CP_A16Z(db + 4096u, zz.Blo + so, sz);
        }
        CP_COMMIT();
    };

    float acc[4][2][4];
    #pragma unroll
    for (int i = 0; i < 4; i++)
        #pragma unroll
        for (int j = 0; j < 2; j++)
            #pragma unroll
            for (int q = 0; q < 4; q++) acc[i][j][q] = 0.f;

    issue(0); issue(1);
    for (int it = 0; it < nt; ++it) {
        if (it + 1 < nt) { CP_WAIT(1); }
        else             { CP_WAIT(0); }   // tail: ALL groups complete
        __syncthreads();
        if (it + 2 < nt) issue(it + 2);
        uint32_t base = sb + (uint32_t)(it % 3) * N64_STAGE;

        #pragma unroll
        for (int h = 0; h < 2; ++h) {
            uint32_t a_hi[16], b_hi[4], tmp[16];
            int lrow = lane & 15, lchk = lane >> 4;
            uint32_t ad[4];
            #pragma unroll
            for (int mf = 0; mf < 4; ++mf) {
                ad[mf] = base + (uint32_t)((wm * 64 + mf * 16 + lrow) * 80 + (h * 2 + lchk) * 16);
                LDSM_X4(&a_hi[mf * 4], ad[mf]);
            }
            int krow = h * 16 + (lane & 15);
            int clog = wn * 2 + (lane >> 4);
            uint32_t bd = base + 20480u + (uint32_t)(krow * 128 + ((clog ^ (krow & 7)) * 16));
            LDSM_X4_T(b_hi, bd);
            #pragma unroll
            for (int mf = 0; mf < 4; ++mf)
                #pragma unroll
                for (int nf = 0; nf < 2; ++nf)
                    MMA_BF16(acc[mf][nf], &a_hi[mf * 4], (&b_hi[nf * 2]));
            #pragma unroll
            for (int mf = 0; mf < 4; ++mf) LDSM_X4(&tmp[mf * 4], ad[mf] + 10240u);
            #pragma unroll
            for (int mf = 0; mf < 4; ++mf)
                #pragma unroll
                for (int nf = 0; nf < 2; ++nf)
                    MMA_BF16(acc[mf][nf], &tmp[mf * 4], (&b_hi[nf * 2]));
            LDSM_X4_T(b_hi, bd + 4096u);
            #pragma unroll
            for (int mf = 0; mf < 4; ++mf)
                #pragma unroll
                for (int nf = 0; nf < 2; ++nf)
                    MMA_BF16(acc[mf][nf], &a_hi[mf * 4], (&b_hi[nf * 2]));
        }
    }

    int rbase = lane >> 2;
    int cbase = (lane & 3) * 2;
    #pragma unroll
    for (int mf = 0; mf < 4; ++mf) {
        #pragma unroll
        for (int nf = 0; nf < 2; ++nf) {
            int col = n0 + wn * 16 + nf * 8 + cbase;
            if (col >= N) continue;
            float b0 = 0.f, b1 = 0.f;
            if (zz.bias) { b0 = zz.bias[col]; b1 = zz.bias[col + 1]; }
            #pragma unroll
            for (int half = 0; half < 2; ++half) {
                int row = m0 + wm * 64 + mf * 16 + rbase + half * 8;
                float t0 = ep_act(acc[mf][nf][half * 2 + 0] + b0, zz.act);
                float t1 = ep_act(acc[mf][nf][half * 2 + 1] + b1, zz.act);
                if (!zz.Chi) {
                    *(float2*)(zz.C + (size_t)row * N + col) = make_float2(t0, t1);
                } else {
                    uint32_t hw, lw;
                    cvt_split2(t0, t1, hw, lw);
                    *(uint32_t*)(zz.Chi + (size_t)row * N + col) = hw;
                    *(uint32_t*)(zz.Clo + (size_t)row * N + col) = lw;
                }
            }
        }
    }
}

// ---------------------------------------------------------------- fused projections: big3 (TN128) + stage1/gA (TN64), striped 2:1
#define PROJ_SMEM 87040
__global__ __launch_bounds__(256, 2)
void proj_all(GemmBatch big, GemmBatch lora) {
    extern __shared__ char dsm[];
    int g = blockIdx.x;
    int r = g % 3;
    if (r < 2) {
        int t = (g / 3) * 2 + r;
        GemmZ zz = big.z[t >> 9];
        gemm128_body(zz, ((t >> 3) & 63) * 128, (t & 7) * 128, dsm);
    } else {
        int t = g / 3;
        GemmZ zz = lora.z[t / 192];
        gemm64_body(zz, ((t / 3) % 64) * 128, (t % 3) * 64, dsm);
    }
}

// ---------------------------------------------------------------- kernel: batched weight split
struct ConvJob { const float* src; int off; int sz; };
struct ConvBatch { ConvJob j[12]; };
__global__ void conv_split_all(ConvBatch cb) {
    ConvJob jb = cb.j[blockIdx.y];
    int np = jb.sz >> 1;
    int p = blockIdx.x * blockDim.x + threadIdx.x;
    if (p >= np) return;
    float2 v = ((const float2*)jb.src)[p];
    uint32_t hw, lw;
    cvt_split2(v.x, v.y, hw, lw);
    ((uint32_t*)(g_wsplit + jb.off))[p] = hw;
    ((uint32_t*)(g_wsplit + jb.off + jb.sz))[p] = lw;
}

// ---------------------------------------------------------------- kernel: token-shift mixes -> bf16 hi/lo planes
__global__ void prep6_kernel(const float* __restrict__ x,
                             const float* __restrict__ mr, const float* __restrict__ mw,
                             const float* __restrict__ mk, const float* __restrict__ mv,
                             const float* __restrict__ ma, const float* __restrict__ mg) {
    int p = blockIdx.x * blockDim.x + threadIdx.x;
    if (p >= BTH / 2) return;
    int idx = p * 2;
    int ch = idx & (Hh - 1);
    int tok = idx >> 10;
    int t = tok & (Tt - 1);
    float x0 = x[idx], x1 = x[idx + 1];
    float d0 = ((t == 0) ? 0.f : x[idx - Hh]) - x0;
    float d1 = ((t == 0) ? 0.f : x[idx - Hh + 1]) - x1;

    float* dsts[6] = { g_xr, g_xw, g_xk, g_xv, g_xa, g_xg };
    const float* ms[6] = { mr, mw, mk, mv, ma, mg };
    #pragma unroll
    for (int i = 0; i < 6; ++i) {
        float v0 = x0 + d0 * ms[i][ch];
        float v1 = x1 + d1 * ms[i][ch + 1];
        uint32_t hw, lw;
        cvt_split2(v0, v1, hw, lw);
        __nv_bfloat16* base = (__nv_bfloat16*)dsts[i];
        ((uint32_t*)base)[p] = hw;
        ((uint32_t*)(base + BTH))[p] = lw;
    }
}

// ---------------------------------------------------------------- kernel: per-(token,head) prep (8 warps/block)
__global__ __launch_bounds__(256)
void prep_scan_kernel(const float* __restrict__ v_first,
                      const float* __restrict__ k_k,
                      const float* __restrict__ k_a) {
    int bh = blockIdx.x * 8 + (threadIdx.x >> 5);
    int lane = threadIdx.x & 31;
    int tok = bh >> 4;
    int h = bh & 15;
    int b = tok >> 11;
    int t = tok & (Tt - 1);
    int ofs = tok * Hh + h * 64;
    int hofs = (((b * NHh + h) * Tt) + t) * 64;
    int hd0 = h * 64 + lane, hd1 = hd0 + 32;

    float kv0 = g_k[ofs + lane],  kv1 = g_k[ofs + lane + 32];
    float av0 = g_al[ofs + lane], av1 = g_al[ofs + lane + 32];
    float kk0 = kv0 * k_k[hd0],   kk1 = kv1 * k_k[hd1];
    float ss = warp_sum(kk0 * kk0 + kk1 * kk1);
    float inv = 1.f / fmaxf(sqrtf(ss), 1e-12f);

    float r0 = g_r[ofs + lane],   r1 = g_r[ofs + lane + 32];
    float w0 = g_wl[ofs + lane],  w1 = g_wl[ofs + lane + 32];
    float vv0 = g_v0[ofs + lane], vv1 = g_v0[ofs + lane + 32];
    float vl0 = g_vl[ofs + lane], vl1 = g_vl[ofs + lane + 32];
    float vf0 = v_first[ofs + lane], vf1 = v_first[ofs + lane + 32];

    #pragma unroll
    for (int e = 0; e < 2; e++) {
        int d = lane + e * 32;
        float kv = e ? kv1 : kv0;
        float aa = e ? av1 : av0;
        float kkn = (e ? kk1 : kk0) * inv;
        g_aH[hofs + d] = -kkn;
        g_bH[hofs + d] = kkn * aa;
        g_kH[hofs + d] = kv * (1.f + (aa - 1.f) * k_a[h * 64 + d]);
        g_rH[hofs + d] = e ? r1 : r0;
        g_wHe[hofs + d] = __expf(DECAYC * (e ? w1 : w0));
        float v0v = e ? vv1 : vv0;
        g_vH[hofs + d] = v0v + (e ? vl1 : vl0) * ((e ? vf1 : vf0) - v0v);
    }
}

// ---------------------------------------------------------------- kernel: WKV7 scan — warp-private rings, NO block barrier
// Full in-warp o reduction (o not loop-carried; shfls cost issue slots only).
__global__ __launch_bounds__(128)
void scan_kernel() {
    int head = blockIdx.x >> 2;
    int quarter = blockIdx.x & 3;
    size_t base = (size_t)head * Tt * 64;
    int tid = threadIdx.x;
    int wid = tid >> 5, lane = tid & 31;
    int v = quarter * 16 + wid * 4 + (lane >> 3);  // global 0..63
    int c = lane & 7;
    int co = c * 8;

    __shared__ __align__(16) float ring[4][6][384];

    const float* srcs[6] = { g_rH + base, g_wHe + base, g_kH + base,
                             g_vH + base, g_aH + base, g_bH + base };
    const float* sp[3];
    uint32_t dof[3];
    #pragma unroll
    for (int q = 0; q < 3; ++q) {
        int g = lane + 32 * q;
        sp[q] = srcs[g >> 4] + (g & 15) * 4;
        dof[q] = (uint32_t)(g * 16);
    }
    uint32_t dbase = smem_u32(&ring[wid][0][0]);

    auto issue = [&](int tt, int slot) {
        uint32_t d = dbase + (uint32_t)slot * 1536u;
        #pragma unroll
        for (int q = 0; q < 3; ++q) CP_A16(d + dof[q], sp[q] + (size_t)tt * 64);
        CP_COMMIT();
    };

    #pragma unroll
    for (int s = 0; s < 5; ++s) issue(s, s);

    float S[8];
    #pragma unroll
    for (int j = 0; j < 8; j++) S[j] = 0.f;

    float* outp = g_oH + base + v;

    for (int t = 0; t < Tt; ++t) {
        CP_WAIT(4);
        int tt = (t + 5 < Tt) ? t + 5 : Tt - 1;
        issue(tt, (t + 5) % 6);             // overwrites slot (t-1)%6 — in-warp order safe

        const float* cu = &ring[wid][t % 6][0];
        float rL[8], wL[8], kL[8], aL[8], bL[8];
        #pragma unroll
        for (int q = 0; q < 2; ++q) {
            *(float4*)(rL + q * 4) = *(const float4*)(cu + co + q * 4);
            *(float4*)(wL + q * 4) = *(const float4*)(cu + 64 + co + q * 4);
            *(float4*)(kL + q * 4) = *(const float4*)(cu + 128 + co + q * 4);
            *(float4*)(aL + q * 4) = *(const float4*)(cu + 256 + co + q * 4);
            *(float4*)(bL + q * 4) = *(const float4*)(cu + 320 + co + q * 4);
        }
        float vt = cu[192 + v];

        float sa0 = 0.f, sa1 = 0.f;
        #pragma unroll
        for (int j = 0; j < 4; j++) {
            sa0 += S[j] * aL[j];
            sa1 += S[j + 4] * aL[j + 4];
        }
        float sa = sa0 + sa1;
        sa += __shfl_xor_sync(0xffffffffu, sa, 1);
        sa += __shfl_xor_sync(0xffffffffu, sa, 2);
        sa += __shfl_xor_sync(0xffffffffu, sa, 4);

        float o0 = 0.f, o1 = 0.f;
        #pragma unroll
        for (int j = 0; j < 4; j++) {
            float s0 = S[j] * wL[j] + sa * bL[j] + vt * kL[j];
            float s1 = S[j + 4] * wL[j + 4] + sa * bL[j + 4] + vt * kL[j + 4];
            S[j] = s0; S[j + 4] = s1;
            o0 += s0 * rL[j];
            o1 += s1 * rL[j + 4];
        }
        float o = o0 + o1;
        o += __shfl_xor_sync(0xffffffffu, o, 1);
        o += __shfl_xor_sync(0xffffffffu, o, 2);
        o += __shfl_xor_sync(0xffffffffu, o, 4);
        if (c == 0) outp[(size_t)t * 64] = o;
    }
}

// ---------------------------------------------------------------- kernel: groupnorm + corr + gate -> y bf16 planes
__global__ __launch_bounds__(256)
void out_stage_kernel(const float* __restrict__ r_k,
                      const float* __restrict__ gn_w,
                      const float* __restrict__ gn_b) {
    int bh = blockIdx.x * 8 + (threadIdx.x >> 5);
    int lane = threadIdx.x & 31;
    int tok = bh >> 4;
    int h = bh & 15;
    int b = tok >> 11;
    int t = tok & (Tt - 1);
    int ofs = tok * Hh + h * 64;
    int hofs = (((b * NHh + h) * Tt) + t) * 64;
    int d0 = lane * 2, d1 = d0 + 1;

    float2 ov = *(const float2*)(g_oH + hofs + d0);
    float o0 = ov.x, o1 = ov.y;

    float r0 = g_rH[hofs + d0], r1 = g_rH[hofs + d1];
    float k0 = g_kH[hofs + d0], k1 = g_kH[hofs + d1];
    float v0 = g_vH[hofs + d0], v1 = g_vH[hofs + d1];

    float mu = warp_sum(o0 + o1) * (1.f / 64.f);
    float sq = warp_sum(o0 * o0 + o1 * o1) * (1.f / 64.f);
    float var = sq - mu * mu;
    float rstd = rsqrtf(var + GN_EPS);
    float dot = warp_sum(r0 * k0 * r_k[h * 64 + d0] + r1 * k1 * r_k[h * 64 + d1]);

    float gl0 = g_gl[ofs + d0], gl1 = g_gl[ofs + d1];
    float on0 = (o0 - mu) * rstd * gn_w[h * 64 + d0] + gn_b[h * 64 + d0];
    float on1 = (o1 - mu) * rstd * gn_w[h * 64 + d1] + gn_b[h * 64 + d1];
    float y0 = (on0 + dot * v0) * gl0;
    float y1 = (on1 + dot * v1) * gl1;

    uint32_t hw, lw;
    cvt_split2(y0, y1, hw, lw);
    __nv_bfloat16* ybase = (__nv_bfloat16*)g_y;
    ((uint32_t*)ybase)[(ofs + d0) >> 1] = hw;
    ((uint32_t*)(ybase + BTH))[(ofs + d0) >> 1] = lw;
}

// ---------------------------------------------------------------- launch
extern "C" void kernel_launch(void* const* d_in, const int* in_sizes, int n_in,
                              void* d_out, int out_size) {
    const float* x       = (const float*)d_in[0];
    const float* v_first = (const float*)d_in[1];
    const float* x_r = (const float*)d_in[2];
    const float* x_w = (const float*)d_in[3];
    const float* x_k = (const float*)d_in[4];
    const float* x_v = (const float*)d_in[5];
    const float* x_a = (const float*)d_in[6];
    const float* x_g = (const float*)d_in[7];
    const float* k_k = (const float*)d_in[8];
    const float* k_a = (const float*)d_in[9];
    const float* r_k = (const float*)d_in[10];
    const float* W_r = (const float*)d_in[11];
    const float* W_k = (const float*)d_in[12];
    const float* W_v = (const float*)d_in[13];
    const float* W_o = (const float*)d_in[14];
    const float* wA  = (const float*)d_in[15];
    const float* wB  = (const float*)d_in[16];
    const float* wb  = (const float*)d_in[17];
    const float* vA  = (const float*)d_in[18];
    const float* vB  = (const float*)d_in[19];
    const float* vb  = (const float*)d_in[20];
    const float* aA  = (const float*)d_in[21];
    const float* aB  = (const float*)d_in[22];
    const float* ab  = (const float*)d_in[23];
    const float* gA  = (const float*)d_in[24];
    const float* gB  = (const float*)d_in[25];
    const float* gn_w = (const float*)d_in[26];
    const float* gn_b = (const float*)d_in[27];
    float* out = (float*)d_out;

    float *p_xr, *p_xw, *p_xk, *p_xv, *p_xa, *p_xg;
    float *p_r, *p_k, *p_v0, *p_hw, *p_hv, *p_ha, *p_hg;
    float *p_wl, *p_vl, *p_al, *p_gl;
    __nv_bfloat16* p_ws;
    cudaGetSymbolAddress((void**)&p_xr, g_xr);
    cudaGetSymbolAddress((void**)&p_xw, g_xw);
    cudaGetSymbolAddress((void**)&p_xk, g_xk);
    cudaGetSymbolAddress((void**)&p_xv, g_xv);
    cudaGetSymbolAddress((void**)&p_xa, g_xa);
    cudaGetSymbolAddress((void**)&p_xg, g_xg);
    cudaGetSymbolAddress((void**)&p_r,  g_r);
    cudaGetSymbolAddress((void**)&p_k,  g_k);
    cudaGetSymbolAddress((void**)&p_v0, g_v0);
    cudaGetSymbolAddress((void**)&p_hw, g_hw);
    cudaGetSymbolAddress((void**)&p_hv, g_hv);
    cudaGetSymbolAddress((void**)&p_ha, g_ha);
    cudaGetSymbolAddress((void**)&p_hg, g_hg);
    cudaGetSymbolAddress((void**)&p_wl, g_wl);
    cudaGetSymbolAddress((void**)&p_vl, g_vl);
    cudaGetSymbolAddress((void**)&p_al, g_al);
    cudaGetSymbolAddress((void**)&p_gl, g_gl);
    cudaGetSymbolAddress((void**)&p_ws, g_wsplit);

    cudaFuncSetAttribute(gemm_mma, cudaFuncAttributeMaxDynamicSharedMemorySize, G_SMEM);
    cudaFuncSetAttribute(proj_all, cudaFuncAttributeMaxDynamicSharedMemorySize, PROJ_SMEM);

    // ---- weight splits: one launch
    {
        ConvBatch cb = {{
            {W_r, OFF_WR, SZ_BIG}, {W_k, OFF_WK, SZ_BIG}, {W_v, OFF_WV, SZ_BIG}, {W_o, OFF_WO, SZ_BIG},
            {wA, OFF_wA, SZ_LORA}, {vA, OFF_vA, SZ_LORA}, {aA, OFF_aA, SZ_LORA}, {gA, OFF_gA, SZ_G},
            {wB, OFF_wB, SZ_LORA}, {vB, OFF_vB, SZ_LORA}, {aB, OFF_aB, SZ_LORA}, {gB, OFF_gB, SZ_G},
        }};
        conv_split_all<<<dim3((SZ_BIG / 2 + 255) / 256, 12), 256>>>(cb);
    }

    // ---- token-shift mixes
    prep6_kernel<<<(BTH / 2 + 255) / 256, 256>>>(x, x_r, x_w, x_k, x_v, x_a, x_g);

    auto planes = [&](float* f) { return (__nv_bfloat16*)f; };
    GemmZ Z0 = {};

    // ---- FUSED projections: big3 (r,k,v0) + LoRA stage1/gA, one launch
    {
        GemmBatch big = {}, lora = {};
        __nv_bfloat16* a3[3] = { planes(p_xr), planes(p_xk), planes(p_xv) };
        int w3[3] = { OFF_WR, OFF_WK, OFF_WV };
        float* c3[3] = { p_r, p_k, p_v0 };
        for (int i = 0; i < 3; ++i) {
            big.z[i] = Z0;
            big.z[i].Ahi = a3[i]; big.z[i].Alo = a3[i] + BTH;
            big.z[i].Bhi = p_ws + w3[i]; big.z[i].Blo = p_ws + w3[i] + SZ_BIG;
            big.z[i].C = c3[i]; big.z[i].N = 1024; big.z[i].K = 1024;
        }
        __nv_bfloat16* a4[4] = { planes(p_xw), planes(p_xv), planes(p_xa), planes(p_xg) };
        int w4[4] = { OFF_wA, OFF_vA, OFF_aA, OFF_gA };
        int ws4[4] = { SZ_LORA, SZ_LORA, SZ_LORA, SZ_G };
        float* c4[4] = { p_hw, p_hv, p_ha, p_hg };
        int act4[4] = { 1, 0, 0, 2 };
        int nn4[4] = { 64, 64, 64, 160 };
        int cs4[4] = { BT * 64, BT * 64, BT * 64, BT * 160 };
        for (int i = 0; i < 4; ++i) {
            lora.z[i] = Z0;
            lora.z[i].Ahi = a4[i]; lora.z[i].Alo = a4[i] + BTH;
            lora.z[i].Bhi = p_ws + w4[i]; lora.z[i].Blo = p_ws + w4[i] + ws4[i];
            lora.z[i].Chi = planes(c4[i]); lora.z[i].Clo = planes(c4[i]) + cs4[i];
            lora.z[i].act = act4[i]; lora.z[i].N = nn4[i]; lora.z[i].K = 1024;
        }
        proj_all<<<2304, 256, PROJ_SMEM>>>(big, lora);
    }

    // ---- stage2 (wl,vl,al; K=64) + gB (gl; K=160) in ONE launch, per-z K
    {
        GemmBatch gbm = {};
        float* a3[3] = { p_hw, p_hv, p_ha };
        int w3[3] = { OFF_wB, OFF_vB, OFF_aB };
        float* c3[3] = { p_wl, p_vl, p_al };
        const float* b3[3] = { wb, vb, ab };
        for (int i = 0; i < 3; ++i) {
            gbm.z[i] = Z0;
            gbm.z[i].Ahi = planes(a3[i]); gbm.z[i].Alo = planes(a3[i]) + BT * 64;
            gbm.z[i].Bhi = p_ws + w3[i]; gbm.z[i].Blo = p_ws + w3[i] + SZ_LORA;
            gbm.z[i].C = c3[i]; gbm.z[i].bias = b3[i]; gbm.z[i].act = 2;
            gbm.z[i].N = 1024; gbm.z[i].K = 64;
        }
        gbm.z[3] = Z0;
        gbm.z[3].Ahi = planes(p_hg); gbm.z[3].Alo = planes(p_hg) + BT * 160;
        gbm.z[3].Bhi = p_ws + OFF_gB; gbm.z[3].Blo = p_ws + OFF_gB + SZ_G;
        gbm.z[3].C = p_gl; gbm.z[3].N = 1024; gbm.z[3].K = 160;
        gemm_mma<<<dim3(8, 64, 4), 256, G_SMEM>>>(gbm, BT);
    }

    // ---- head-layout prep (x-bufs dead -> reused)
    prep_scan_kernel<<<BT * NHh / 8, 256>>>(v_first, k_k, k_a);

    // ---- sequential scan (warp-private rings, barrier-free, full o reduce)
    scan_kernel<<<Bb * NHh * 4, 128>>>();

    // ---- groupnorm + corr + gate -> y bf16 planes (g_vl, dead)
    out_stage_kernel<<<BT * NHh / 8, 256>>>(r_k, gn_w, gn_b);

    // ---- output projection
    {
        GemmBatch gbm = {};
        gbm.z[0] = Z0;
        gbm.z[0].Ahi = planes(p_vl); gbm.z[0].Alo = planes(p_vl) + BTH;
        gbm.z[0].Bhi = p_ws + OFF_WO; gbm.z[0].Blo = p_ws + OFF_WO + SZ_BIG;
        gbm.z[0].C = out; gbm.z[0].N = 1024; gbm.z[0].K = 1024;
        gemm_mma<<<dim3(8, 64, 1), 256, G_SMEM>>>(gbm, BT);
    }

    (void)in_sizes; (void)n_in; (void)out_size;
}

// round 15
// speedup vs baseline: 1.0665x; 1.0665x over previous
#include <cuda_runtime.h>
#include <cuda_bf16.h>
#include <math.h>
#include <stdint.h>

// ---------------------------------------------------------------- constants
#define Bb   4
#define Tt   2048
#define Hh   1024
#define NHh  16
#define HDh  64
#define BT   (Bb*Tt)          // 8192 tokens
#define BTH  (BT*Hh)          // 8388608
#define DECAYC (-0.6065306597126334f)
#define GN_EPS (HDh*1e-5f)    // 6.4e-4

// ---------------------------------------------------------------- scratch (aliased by liveness)
__device__ __align__(128) float g_xr[BTH], g_xw[BTH], g_xk[BTH], g_xv[BTH], g_xa[BTH], g_xg[BTH];
__device__ __align__(128) float g_r[BTH], g_k[BTH], g_v0[BTH];
__device__ __align__(128) float g_hw[BT*64], g_hv[BT*64], g_ha[BT*64], g_hg[BT*160];
__device__ __align__(128) float g_wl[BTH], g_vl[BTH], g_al[BTH], g_gl[BTH];

// weight split scratch (bf16 hi/lo planes, per-weight: hi at off, lo at off+size)
#define SZ_BIG 1048576
#define SZ_LORA 65536
#define SZ_G  163840
#define OFF_WR 0
#define OFF_WK 2097152
#define OFF_WV 4194304
#define OFF_WO 6291456
#define OFF_wA 8388608
#define OFF_vA 8519680
#define OFF_aA 8650752
#define OFF_gA 8781824
#define OFF_wB 9109504
#define OFF_vB 9240576
#define OFF_aB 9371648
#define OFF_gB 9502720
#define WSPLIT_TOTAL 9830400
__device__ __align__(128) __nv_bfloat16 g_wsplit[WSPLIT_TOTAL];

#define g_rH  g_xr
#define g_wHe g_xw
#define g_kH  g_xk
#define g_vH  g_xv
#define g_aH  g_xa
#define g_bH  g_xg
#define g_y   g_vl
// scan partial-o planes: reuse buffers dead after prep_scan
#define g_P0  g_r
#define g_P1  g_k
#define g_P2  g_v0
#define g_P3  g_al

// ---------------------------------------------------------------- helpers
__device__ __forceinline__ uint32_t smem_u32(const void* p) {
    uint32_t a;
    asm("{ .reg .u64 t; cvta.to.shared.u64 t, %1; cvt.u32.u64 %0, t; }" : "=r"(a) : "l"(p));
    return a;
}
__device__ __forceinline__ float warp_sum(float v) {
    #pragma unroll
    for (int o = 16; o > 0; o >>= 1) v += __shfl_xor_sync(0xffffffffu, v, o);
    return v;
}
__device__ __forceinline__ void cvt_split2(float a, float b, uint32_t& hi, uint32_t& lo) {
    __nv_bfloat162 h = __float22bfloat162_rn(make_float2(a, b));
    float2 hf = __bfloat1622float2(h);
    __nv_bfloat162 l = __float22bfloat162_rn(make_float2(a - hf.x, b - hf.y));
    hi = *(uint32_t*)&h;
    lo = *(uint32_t*)&l;
}

#define CP_A16(dst, src)      asm volatile("cp.async.cg.shared.global [%0], [%1], 16;" :: "r"(dst), "l"(src) : "memory")
#define CP_A16Z(dst, src, sz) asm volatile("cp.async.cg.shared.global [%0], [%1], 16, %2;" :: "r"(dst), "l"(src), "r"(sz) : "memory")
#define CP_COMMIT()           asm volatile("cp.async.commit_group;" ::: "memory")
#define CP_WAIT(n)            asm volatile("cp.async.wait_group %0;" :: "n"(n) : "memory")

#define LDSM_X4(r, addr) \
    asm volatile("ldmatrix.sync.aligned.m8n8.x4.shared.b16 {%0,%1,%2,%3}, [%4];" \
        : "=r"((r)[0]),"=r"((r)[1]),"=r"((r)[2]),"=r"((r)[3]) : "r"(addr))
#define LDSM_X4_T(r, addr) \
    asm volatile("ldmatrix.sync.aligned.m8n8.x4.trans.shared.b16 {%0,%1,%2,%3}, [%4];" \
        : "=r"((r)[0]),"=r"((r)[1]),"=r"((r)[2]),"=r"((r)[3]) : "r"(addr))

#define MMA_BF16(d, a, b) \
    asm volatile("mma.sync.aligned.m16n8k16.row.col.f32.bf16.bf16.f32 " \
        "{%0,%1,%2,%3}, {%4,%5,%6,%7}, {%8,%9}, {%0,%1,%2,%3};" \
        : "+f"((d)[0]),"+f"((d)[1]),"+f"((d)[2]),"+f"((d)[3]) \
        : "r"((a)[0]),"r"((a)[1]),"r"((a)[2]),"r"((a)[3]), "r"((b)[0]),"r"((b)[1]))

struct GemmZ {
    const __nv_bfloat16 *Ahi, *Alo, *Bhi, *Blo;
    float* C;
    __nv_bfloat16 *Chi, *Clo;
    const float* bias;
    int act;            // 0 none, 1 tanh, 2 sigmoid
    int N;              // per-z N
    int K;              // per-z K
};
struct GemmBatch { GemmZ z[4]; };

__device__ __forceinline__ float ep_act(float t, int act) {
    if (act == 1) return tanhf(t);
    if (act == 2) return 1.f / (1.f + __expf(-t));
    return t;
}

// ---------------------------------------------------------------- TN=128 GEMM body (proven)
#define G_STAGE 36864u
#define G_SMEM  (2*36864 + 1024)

__device__ __forceinline__ void gemm128_body(const GemmZ& zz, int m0, int n0, char* dsm) {
    uint32_t sb = (smem_u32(dsm) + 1023u) & ~1023u;
    int N = zz.N, K = zz.K;
    int tid = threadIdx.x;
    int wid = tid >> 5, lane = tid & 31;
    int wm = wid >> 2, wn = wid & 3;
    int nt = K >> 5;

    auto issue = [&](int it) {
        uint32_t base = sb + (uint32_t)(it & 1) * G_STAGE;
        int k0 = it << 5;
        #pragma unroll
        for (int s = 0; s < 2; ++s) {
            int ca = tid + s * 256;
            int row = ca >> 2, cc = ca & 3;
            size_t so = (size_t)(m0 + row) * K + k0 + cc * 8;
            uint32_t da = base + (uint32_t)(row * 80 + cc * 16);
            CP_A16(da, zz.Ahi + so);
            CP_A16(da + 10240u, zz.Alo + so);
        }
        #pragma unroll
        for (int s = 0; s < 2; ++s) {
            int cb = tid + s * 256;
            int kk = cb >> 4, j = cb & 15;
            int gn = n0 + j * 8;
            uint32_t sz = (gn < N) ? 16u : 0u;
            size_t so = (size_t)(k0 + kk) * N + ((gn < N) ? gn : 0);
            uint32_t db = base + 20480u + (uint32_t)(kk * 256 + ((j ^ (kk & 7)) * 16));
            CP_A16Z(db, zz.Bhi + so, sz);
            CP_A16Z(db + 8192u, zz.Blo + so, sz);
        }
        CP_COMMIT();
    };

    float acc[4][4][4];
    #pragma unroll
    for (int i = 0; i < 4; i++)
        #pragma unroll
        for (int j = 0; j < 4; j++)
            #pragma unroll
            for (int q = 0; q < 4; q++) acc[i][j][q] = 0.f;

    issue(0);
    for (int it = 0; it < nt; ++it) {
        if (it + 1 < nt) { issue(it + 1); CP_WAIT(1); }
        else             { CP_WAIT(0); }
        __syncthreads();
        uint32_t base = sb + (uint32_t)(it & 1) * G_STAGE;

        #pragma unroll
        for (int h = 0; h < 2; ++h) {
            uint32_t a_hi[16], b_hi[8], tmp[16];
            int lrow = lane & 15, lchk = lane >> 4;
            uint32_t ad[4];
            #pragma unroll
            for (int mf = 0; mf < 4; ++mf) {
                ad[mf] = base + (uint32_t)((wm * 64 + mf * 16 + lrow) * 80 + (h * 2 + lchk) * 16);
                LDSM_X4(&a_hi[mf * 4], ad[mf]);
            }
            int krow = h * 16 + (lane & 15);
            uint32_t bd[2];
            #pragma unroll
            for (int pr = 0; pr < 2; ++pr) {
                int nabs = wn * 32 + pr * 16 + (lane >> 4) * 8;
                int clog = nabs >> 3;
                bd[pr] = base + 20480u + (uint32_t)(krow * 256 + ((clog ^ (krow & 7)) * 16));
                LDSM_X4_T(&b_hi[pr * 4], bd[pr]);
            }
            #pragma unroll
            for (int mf = 0; mf < 4; ++mf)
                #pragma unroll
                for (int nf = 0; nf < 4; ++nf)
                    MMA_BF16(acc[mf][nf], &a_hi[mf * 4], (&b_hi[(nf >> 1) * 4 + (nf & 1) * 2]));
            #pragma unroll
            for (int mf = 0; mf < 4; ++mf) LDSM_X4(&tmp[mf * 4], ad[mf] + 10240u);
            #pragma unroll
            for (int mf = 0; mf < 4; ++mf)
                #pragma unroll
                for (int nf = 0; nf < 4; ++nf)
                    MMA_BF16(acc[mf][nf], &tmp[mf * 4], (&b_hi[(nf >> 1) * 4 + (nf & 1) * 2]));
            #pragma unroll
            for (int pr = 0; pr < 2; ++pr) LDSM_X4_T(&b_hi[pr * 4], bd[pr] + 8192u);
            #pragma unroll
            for (int mf = 0; mf < 4; ++mf)
                #pragma unroll
                for (int nf = 0; nf < 4; ++nf)
                    MMA_BF16(acc[mf][nf], &a_hi[mf * 4], (&b_hi[(nf >> 1) * 4 + (nf & 1) * 2]));
        }
        __syncthreads();
    }

    int rbase = lane >> 2;
    int cbase = (lane & 3) * 2;
    #pragma unroll
    for (int mf = 0; mf < 4; ++mf) {
        #pragma unroll
        for (int nf = 0; nf < 4; ++nf) {
            int col = n0 + wn * 32 + nf * 8 + cbase;
            if (col >= N) continue;
            float b0 = 0.f, b1 = 0.f;
            if (zz.bias) { b0 = zz.bias[col]; b1 = zz.bias[col + 1]; }
            #pragma unroll
            for (int half = 0; half < 2; ++half) {
                int row = m0 + wm * 64 + mf * 16 + rbase + half * 8;
                float t0 = ep_act(acc[mf][nf][half * 2 + 0] + b0, zz.act);
                float t1 = ep_act(acc[mf][nf][half * 2 + 1] + b1, zz.act);
                if (!zz.Chi) {
                    *(float2*)(zz.C + (size_t)row * N + col) = make_float2(t0, t1);
                } else {
                    uint32_t hw, lw;
                    cvt_split2(t0, t1, hw, lw);
                    *(uint32_t*)(zz.Chi + (size_t)row * N + col) = hw;
                    *(uint32_t*)(zz.Clo + (size_t)row * N + col) = lw;
                }
            }
        }
    }
}

__global__ __launch_bounds__(256, 2)
void gemm_mma(GemmBatch gb, int M) {
    extern __shared__ char dsm[];
    GemmZ zz = gb.z[blockIdx.z];
    gemm128_body(zz, blockIdx.y * 128, blockIdx.x * 128, dsm);
}

// ---------------------------------------------------------------- TN=64 GEMM body, 3-stage ring (tail-fixed)
#define N64_STAGE 28672u
#define N64_SMEM  (3*28672 + 1024)

__device__ __forceinline__ void gemm64_body(const GemmZ& zz, int m0, int n0, char* dsm) {
    uint32_t sb = (smem_u32(dsm) + 1023u) & ~1023u;
    int N = zz.N, K = zz.K;
    if (n0 >= N) return;                 // uniform per-block

    int tid = threadIdx.x;
    int wid = tid >> 5, lane = tid & 31;
    int wm = wid >> 2, wn = wid & 3;
    int nt = K >> 5;

    auto issue = [&](int it) {
        uint32_t base = sb + (uint32_t)(it % 3) * N64_STAGE;
        int k0 = it << 5;
        #pragma unroll
        for (int s = 0; s < 2; ++s) {
            int ca = tid + s * 256;
            int row = ca >> 2, cc = ca & 3;
            size_t so = (size_t)(m0 + row) * K + k0 + cc * 8;
            uint32_t da = base + (uint32_t)(row * 80 + cc * 16);
            CP_A16(da, zz.Ahi + so);
            CP_A16(da + 10240u, zz.Alo + so);
        }
        {
            int kk = tid >> 3, j = tid & 7;
            int gn = n0 + j * 8;
            uint32_t sz = (gn < N) ? 16u : 0u;
            size_t so = (size_t)(k0 + kk) * N + ((gn < N) ? gn : 0);
            uint32_t db = base + 20480u + (uint32_t)(kk * 128 + ((j ^ (kk & 7)) * 16));
            CP_A16Z(db, zz.Bhi + so, sz);
            CP_A16Z(db + 4096u, zz.Blo + so, sz);
        }
        CP_COMMIT();
    };

    float acc[4][2][4];
    #pragma unroll
    for (int i = 0; i < 4; i++)
        #pragma unroll
        for (int j = 0; j < 2; j++)
            #pragma unroll
            for (int q = 0; q < 4; q++) acc[i][j][q] = 0.f;

    issue(0); issue(1);
    for (int it = 0; it < nt; ++it) {
        if (it + 1 < nt) { CP_WAIT(1); }
        else             { CP_WAIT(0); }   // tail: ALL groups complete
        __syncthreads();
        if (it + 2 < nt) issue(it + 2);
        uint32_t base = sb + (uint32_t)(it % 3) * N64_STAGE;

        #pragma unroll
        for (int h = 0; h < 2; ++h) {
            uint32_t a_hi[16], b_hi[4], tmp[16];
            int lrow = lane & 15, lchk = lane >> 4;
            uint32_t ad[4];
            #pragma unroll
            for (int mf = 0; mf < 4; ++mf) {
                ad[mf] = base + (uint32_t)((wm * 64 + mf * 16 + lrow) * 80 + (h * 2 + lchk) * 16);
                LDSM_X4(&a_hi[mf * 4], ad[mf]);
            }
            int krow = h * 16 + (lane & 15);
            int clog = wn * 2 + (lane >> 4);
            uint32_t bd = base + 20480u + (uint32_t)(krow * 128 + ((clog ^ (krow & 7)) * 16));
            LDSM_X4_T(b_hi, bd);
            #pragma unroll
            for (int mf = 0; mf < 4; ++mf)
                #pragma unroll
                for (int nf = 0; nf < 2; ++nf)
                    MMA_BF16(acc[mf][nf], &a_hi[mf * 4], (&b_hi[nf * 2]));
            #pragma unroll
            for (int mf = 0; mf < 4; ++mf) LDSM_X4(&tmp[mf * 4], ad[mf] + 10240u);
            #pragma unroll
            for (int mf = 0; mf < 4; ++mf)
                #pragma unroll
                for (int nf = 0; nf < 2; ++nf)
                    MMA_BF16(acc[mf][nf], &tmp[mf * 4], (&b_hi[nf * 2]));
            LDSM_X4_T(b_hi, bd + 4096u);
            #pragma unroll
            for (int mf = 0; mf < 4; ++mf)
                #pragma unroll
                for (int nf = 0; nf < 2; ++nf)
                    MMA_BF16(acc[mf][nf], &a_hi[mf * 4], (&b_hi[nf * 2]));
        }
    }

    int rbase = lane >> 2;
    int cbase = (lane & 3) * 2;
    #pragma unroll
    for (int mf = 0; mf < 4; ++mf) {
        #pragma unroll
        for (int nf = 0; nf < 2; ++nf) {
            int col = n0 + wn * 16 + nf * 8 + cbase;
            if (col >= N) continue;
            float b0 = 0.f, b1 = 0.f;
            if (zz.bias) { b0 = zz.bias[col]; b1 = zz.bias[col + 1]; }
            #pragma unroll
            for (int half = 0; half < 2; ++half) {
                int row = m0 + wm * 64 + mf * 16 + rbase + half * 8;
                float t0 = ep_act(acc[mf][nf][half * 2 + 0] + b0, zz.act);
                float t1 = ep_act(acc[mf][nf][half * 2 + 1] + b1, zz.act);
                if (!zz.Chi) {
                    *(float2*)(zz.C + (size_t)row * N + col) = make_float2(t0, t1);
                } else {
                    uint32_t hw, lw;
                    cvt_split2(t0, t1, hw, lw);
                    *(uint32_t*)(zz.Chi + (size_t)row * N + col) = hw;
                    *(uint32_t*)(zz.Clo + (size_t)row * N + col) = lw;
                }
            }
        }
    }
}

// ---------------------------------------------------------------- fused projections: big3 (TN128) + stage1/gA (TN64), striped 2:1
#define PROJ_SMEM 87040
__global__ __launch_bounds__(256, 2)
void proj_all(GemmBatch big, GemmBatch lora) {
    extern __shared__ char dsm[];
    int g = blockIdx.x;
    int r = g % 3;
    if (r < 2) {
        int t = (g / 3) * 2 + r;
        GemmZ zz = big.z[t >> 9];
        gemm128_body(zz, ((t >> 3) & 63) * 128, (t & 7) * 128, dsm);
    } else {
        int t = g / 3;
        GemmZ zz = lora.z[t / 192];
        gemm64_body(zz, ((t / 3) % 64) * 128, (t % 3) * 64, dsm);
    }
}

// ---------------------------------------------------------------- fused pre: prep6 (blocks 0..16383) + 12 weight splits (9600 blocks)
struct ConvJob { const float* src; int off; int sz; };
struct FusedPre {
    ConvJob j[12];
    int cstart[13];      // prefix block offsets for conv jobs
    const float *x, *mr, *mw, *mk, *mv, *ma, *mg;
};
#define PREP6_BLOCKS 16384

__global__ void fused_pre_kernel(FusedPre fp) {
    int bid = blockIdx.x;
    if (bid < PREP6_BLOCKS) {
        int p = bid * 256 + threadIdx.x;
        if (p >= BTH / 2) return;
        int idx = p * 2;
        int ch = idx & (Hh - 1);
        int tok = idx >> 10;
        int t = tok & (Tt - 1);
        float x0 = fp.x[idx], x1 = fp.x[idx + 1];
        float d0 = ((t == 0) ? 0.f : fp.x[idx - Hh]) - x0;
        float d1 = ((t == 0) ? 0.f : fp.x[idx - Hh + 1]) - x1;

        float* dsts[6] = { g_xr, g_xw, g_xk, g_xv, g_xa, g_xg };
        const float* ms[6] = { fp.mr, fp.mw, fp.mk, fp.mv, fp.ma, fp.mg };
        #pragma unroll
        for (int i = 0; i < 6; ++i) {
            float v0 = x0 + d0 * ms[i][ch];
            float v1 = x1 + d1 * ms[i][ch + 1];
            uint32_t hw, lw;
            cvt_split2(v0, v1, hw, lw);
            __nv_bfloat16* base = (__nv_bfloat16*)dsts[i];
            ((uint32_t*)base)[p] = hw;
            ((uint32_t*)(base + BTH))[p] = lw;
        }
    } else {
        int cid = bid - PREP6_BLOCKS;
        int jj = 0;
        #pragma unroll
        for (int i = 0; i < 12; ++i)
            if (cid >= fp.cstart[i + 1]) jj = i + 1;
        ConvJob jb = fp.j[jj];
        int p = (cid - fp.cstart[jj]) * 256 + threadIdx.x;
        if (p >= (jb.sz >> 1)) return;
        float2 v = ((const float2*)jb.src)[p];
        uint32_t hw, lw;
        cvt_split2(v.x, v.y, hw, lw);
        ((uint32_t*)(g_wsplit + jb.off))[p] = hw;
        ((uint32_t*)(g_wsplit + jb.off + jb.sz))[p] = lw;
    }
}

// ---------------------------------------------------------------- kernel: per-(token,head) prep (8 warps/block)
__global__ __launch_bounds__(256)
void prep_scan_kernel(const float* __restrict__ v_first,
                      const float* __restrict__ k_k,
                      const float* __restrict__ k_a) {
    int bh = blockIdx.x * 8 + (threadIdx.x >> 5);
    int lane = threadIdx.x & 31;
    int tok = bh >> 4;
    int h = bh & 15;
    int b = tok >> 11;
    int t = tok & (Tt - 1);
    int ofs = tok * Hh + h * 64;
    int hofs = (((b * NHh + h) * Tt) + t) * 64;
    int hd0 = h * 64 + lane, hd1 = hd0 + 32;

    float kv0 = g_k[ofs + lane],  kv1 = g_k[ofs + lane + 32];
    float av0 = g_al[ofs + lane], av1 = g_al[ofs + lane + 32];
    float kk0 = kv0 * k_k[hd0],   kk1 = kv1 * k_k[hd1];
    float ss = warp_sum(kk0 * kk0 + kk1 * kk1);
    float inv = 1.f / fmaxf(sqrtf(ss), 1e-12f);

    float r0 = g_r[ofs + lane],   r1 = g_r[ofs + lane + 32];
    float w0 = g_wl[ofs + lane],  w1 = g_wl[ofs + lane + 32];
    float vv0 = g_v0[ofs + lane], vv1 = g_v0[ofs + lane + 32];
    float vl0 = g_vl[ofs + lane], vl1 = g_vl[ofs + lane + 32];
    float vf0 = v_first[ofs + lane], vf1 = v_first[ofs + lane + 32];

    #pragma unroll
    for (int e = 0; e < 2; e++) {
        int d = lane + e * 32;
        float kv = e ? kv1 : kv0;
        float aa = e ? av1 : av0;
        float kkn = (e ? kk1 : kk0) * inv;
        g_aH[hofs + d] = -kkn;
        g_bH[hofs + d] = kkn * aa;
        g_kH[hofs + d] = kv * (1.f + (aa - 1.f) * k_a[h * 64 + d]);
        g_rH[hofs + d] = e ? r1 : r0;
        g_wHe[hofs + d] = __expf(DECAYC * (e ? w1 : w0));
        float v0v = e ? vv1 : vv0;
        g_vH[hofs + d] = v0v + (e ? vl1 : vl0) * ((e ? vf1 : vf0) - v0v);
    }
}

// ---------------------------------------------------------------- kernel: WKV7 scan — warp-private rings, NO block barrier (R13 exact)
__global__ __launch_bounds__(128)
void scan_kernel() {
    int head = blockIdx.x >> 2;
    int quarter = blockIdx.x & 3;
    size_t base = (size_t)head * Tt * 64;
    int tid = threadIdx.x;
    int wid = tid >> 5, lane = tid & 31;
    int v = quarter * 16 + wid * 4 + (lane >> 3);  // global 0..63
    int c = lane & 7;
    int co = c * 8;

    __shared__ __align__(16) float ring[4][6][384];

    const float* srcs[6] = { g_rH + base, g_wHe + base, g_kH + base,
                             g_vH + base, g_aH + base, g_bH + base };
    const float* sp[3];
    uint32_t dof[3];
    #pragma unroll
    for (int q = 0; q < 3; ++q) {
        int g = lane + 32 * q;
        sp[q] = srcs[g >> 4] + (g & 15) * 4;
        dof[q] = (uint32_t)(g * 16);
    }
    uint32_t dbase = smem_u32(&ring[wid][0][0]);

    auto issue = [&](int tt, int slot) {
        uint32_t d = dbase + (uint32_t)slot * 1536u;
        #pragma unroll
        for (int q = 0; q < 3; ++q) CP_A16(d + dof[q], sp[q] + (size_t)tt * 64);
        CP_COMMIT();
    };

    #pragma unroll
    for (int s = 0; s < 5; ++s) issue(s, s);

    float S[8];
    #pragma unroll
    for (int j = 0; j < 8; j++) S[j] = 0.f;

    float* pl[4] = { g_P0, g_P1, g_P2, g_P3 };
    float* pp = pl[c >> 1] + base + v;

    for (int t = 0; t < Tt; ++t) {
        CP_WAIT(4);
        int tt = (t + 5 < Tt) ? t + 5 : Tt - 1;
        issue(tt, (t + 5) % 6);

        const float* cu = &ring[wid][t % 6][0];
        float rL[8], wL[8], kL[8], aL[8], bL[8];
        #pragma unroll
        for (int q = 0; q < 2; ++q) {
            *(float4*)(rL + q * 4) = *(const float4*)(cu + co + q * 4);
            *(float4*)(wL + q * 4) = *(const float4*)(cu + 64 + co + q * 4);
            *(float4*)(kL + q * 4) = *(const float4*)(cu + 128 + co + q * 4);
            *(float4*)(aL + q * 4) = *(const float4*)(cu + 256 + co + q * 4);
            *(float4*)(bL + q * 4) = *(const float4*)(cu + 320 + co + q * 4);
        }
        float vt = cu[192 + v];

        float sa0 = 0.f, sa1 = 0.f;
        #pragma unroll
        for (int j = 0; j < 4; j++) {
            sa0 += S[j] * aL[j];
            sa1 += S[j + 4] * aL[j + 4];
        }
        float sa = sa0 + sa1;
        sa += __shfl_xor_sync(0xffffffffu, sa, 1);
        sa += __shfl_xor_sync(0xffffffffu, sa, 2);
        sa += __shfl_xor_sync(0xffffffffu, sa, 4);

        float o0 = 0.f, o1 = 0.f;
        #pragma unroll
        for (int j = 0; j < 4; j++) {
            float s0 = S[j] * wL[j] + sa * bL[j] + vt * kL[j];
            float s1 = S[j + 4] * wL[j + 4] + sa * bL[j + 4] + vt * kL[j + 4];
            S[j] = s0; S[j + 4] = s1;
            o0 += s0 * rL[j];
            o1 += s1 * rL[j + 4];
        }
        float o = o0 + o1;
        o += __shfl_xor_sync(0xffffffffu, o, 1);   // pair (c, c^1)
        if ((c & 1) == 0) pp[(size_t)t * 64] = o;  // partial j=c>>1
    }
}

// ---------------------------------------------------------------- kernel: groupnorm + corr + gate (sums 4 partials) -> y bf16 planes
__global__ __launch_bounds__(256)
void out_stage_kernel(const float* __restrict__ r_k,
                      const float* __restrict__ gn_w,
                      const float* __restrict__ gn_b) {
    int bh = blockIdx.x * 8 + (threadIdx.x >> 5);
    int lane = threadIdx.x & 31;
    int tok = bh >> 4;
    int h = bh & 15;
    int b = tok >> 11;
    int t = tok & (Tt - 1);
    int ofs = tok * Hh + h * 64;
    int hofs = (((b * NHh + h) * Tt) + t) * 64;
    int d0 = lane * 2, d1 = d0 + 1;

    float2 p0 = *(const float2*)(g_P0 + hofs + d0);
    float2 p1 = *(const float2*)(g_P1 + hofs + d0);
    float2 p2 = *(const float2*)(g_P2 + hofs + d0);
    float2 p3 = *(const float2*)(g_P3 + hofs + d0);
    float o0 = (p0.x + p1.x) + (p2.x + p3.x);
    float o1 = (p0.y + p1.y) + (p2.y + p3.y);

    float r0 = g_rH[hofs + d0], r1 = g_rH[hofs + d1];
    float k0 = g_kH[hofs + d0], k1 = g_kH[hofs + d1];
    float v0 = g_vH[hofs + d0], v1 = g_vH[hofs + d1];

    float mu = warp_sum(o0 + o1) * (1.f / 64.f);
    float sq = warp_sum(o0 * o0 + o1 * o1) * (1.f / 64.f);
    float var = sq - mu * mu;
    float rstd = rsqrtf(var + GN_EPS);
    float dot = warp_sum(r0 * k0 * r_k[h * 64 + d0] + r1 * k1 * r_k[h * 64 + d1]);

    float gl0 = g_gl[ofs + d0], gl1 = g_gl[ofs + d1];
    float on0 = (o0 - mu) * rstd * gn_w[h * 64 + d0] + gn_b[h * 64 + d0];
    float on1 = (o1 - mu) * rstd * gn_w[h * 64 + d1] + gn_b[h * 64 + d1];
    float y0 = (on0 + dot * v0) * gl0;
    float y1 = (on1 + dot * v1) * gl1;

    uint32_t hw, lw;
    cvt_split2(y0, y1, hw, lw);
    __nv_bfloat16* ybase = (__nv_bfloat16*)g_y;
    ((uint32_t*)ybase)[(ofs + d0) >> 1] = hw;
    ((uint32_t*)(ybase + BTH))[(ofs + d0) >> 1] = lw;
}

// ---------------------------------------------------------------- launch
extern "C" void kernel_launch(void* const* d_in, const int* in_sizes, int n_in,
                              void* d_out, int out_size) {
    const float* x       = (const float*)d_in[0];
    const float* v_first = (const float*)d_in[1];
    const float* x_r = (const float*)d_in[2];
    const float* x_w = (const float*)d_in[3];
    const float* x_k = (const float*)d_in[4];
    const float* x_v = (const float*)d_in[5];
    const float* x_a = (const float*)d_in[6];
    const float* x_g = (const float*)d_in[7];
    const float* k_k = (const float*)d_in[8];
    const float* k_a = (const float*)d_in[9];
    const float* r_k = (const float*)d_in[10];
    const float* W_r = (const float*)d_in[11];
    const float* W_k = (const float*)d_in[12];
    const float* W_v = (const float*)d_in[13];
    const float* W_o = (const float*)d_in[14];
    const float* wA  = (const float*)d_in[15];
    const float* wB  = (const float*)d_in[16];
    const float* wb  = (const float*)d_in[17];
    const float* vA  = (const float*)d_in[18];
    const float* vB  = (const float*)d_in[19];
    const float* vb  = (const float*)d_in[20];
    const float* aA  = (const float*)d_in[21];
    const float* aB  = (const float*)d_in[22];
    const float* ab  = (const float*)d_in[23];
    const float* gA  = (const float*)d_in[24];
    const float* gB  = (const float*)d_in[25];
    const float* gn_w = (const float*)d_in[26];
    const float* gn_b = (const float*)d_in[27];
    float* out = (float*)d_out;

    float *p_xr, *p_xw, *p_xk, *p_xv, *p_xa, *p_xg;
    float *p_r, *p_k, *p_v0, *p_hw, *p_hv, *p_ha, *p_hg;
    float *p_wl, *p_vl, *p_al, *p_gl;
    __nv_bfloat16* p_ws;
    cudaGetSymbolAddress((void**)&p_xr, g_xr);
    cudaGetSymbolAddress((void**)&p_xw, g_xw);
    cudaGetSymbolAddress((void**)&p_xk, g_xk);
    cudaGetSymbolAddress((void**)&p_xv, g_xv);
    cudaGetSymbolAddress((void**)&p_xa, g_xa);
    cudaGetSymbolAddress((void**)&p_xg, g_xg);
    cudaGetSymbolAddress((void**)&p_r,  g_r);
    cudaGetSymbolAddress((void**)&p_k,  g_k);
    cudaGetSymbolAddress((void**)&p_v0, g_v0);
    cudaGetSymbolAddress((void**)&p_hw, g_hw);
    cudaGetSymbolAddress((void**)&p_hv, g_hv);
    cudaGetSymbolAddress((void**)&p_ha, g_ha);
    cudaGetSymbolAddress((void**)&p_hg, g_hg);
    cudaGetSymbolAddress((void**)&p_wl, g_wl);
    cudaGetSymbolAddress((void**)&p_vl, g_vl);
    cudaGetSymbolAddress((void**)&p_al, g_al);
    cudaGetSymbolAddress((void**)&p_gl, g_gl);
    cudaGetSymbolAddress((void**)&p_ws, g_wsplit);

    cudaFuncSetAttribute(gemm_mma, cudaFuncAttributeMaxDynamicSharedMemorySize, G_SMEM);
    cudaFuncSetAttribute(proj_all, cudaFuncAttributeMaxDynamicSharedMemorySize, PROJ_SMEM);

    // ---- fused: token-shift mixes + ALL weight splits in ONE launch
    {
        FusedPre fp = {};
        ConvJob jobs[12] = {
            {W_r, OFF_WR, SZ_BIG}, {W_k, OFF_WK, SZ_BIG}, {W_v, OFF_WV, SZ_BIG}, {W_o, OFF_WO, SZ_BIG},
            {wA, OFF_wA, SZ_LORA}, {vA, OFF_vA, SZ_LORA}, {aA, OFF_aA, SZ_LORA}, {gA, OFF_gA, SZ_G},
            {wB, OFF_wB, SZ_LORA}, {vB, OFF_vB, SZ_LORA}, {aB, OFF_aB, SZ_LORA}, {gB, OFF_gB, SZ_G},
        };
        int acc = 0;
        for (int i = 0; i < 12; ++i) {
            fp.j[i] = jobs[i];
            fp.cstart[i] = acc;
            acc += (jobs[i].sz / 2 + 255) / 256;
        }
        fp.cstart[12] = acc;             // 9600
        fp.x = x; fp.mr = x_r; fp.mw = x_w; fp.mk = x_k;
        fp.mv = x_v; fp.ma = x_a; fp.mg = x_g;
        fused_pre_kernel<<<PREP6_BLOCKS + acc, 256>>>(fp);
    }

    auto planes = [&](float* f) { return (__nv_bfloat16*)f; };
    GemmZ Z0 = {};

    // ---- FUSED projections: big3 (r,k,v0) + LoRA stage1/gA, one launch
    {
        GemmBatch big = {}, lora = {};
        __nv_bfloat16* a3[3] = { planes(p_xr), planes(p_xk), planes(p_xv) };
        int w3[3] = { OFF_WR, OFF_WK, OFF_WV };
        float* c3[3] = { p_r, p_k, p_v0 };
        for (int i = 0; i < 3; ++i) {
            big.z[i] = Z0;
            big.z[i].Ahi = a3[i]; big.z[i].Alo = a3[i] + BTH;
            big.z[i].Bhi = p_ws + w3[i]; big.z[i].Blo = p_ws + w3[i] + SZ_BIG;
            big.z[i].C = c3[i]; big.z[i].N = 1024; big.z[i].K = 1024;
        }
        __nv_bfloat16* a4[4] = { planes(p_xw), planes(p_xv), planes(p_xa), planes(p_xg) };
        int w4[4] = { OFF_wA, OFF_vA, OFF_aA, OFF_gA };
        int ws4[4] = { SZ_LORA, SZ_LORA, SZ_LORA, SZ_G };
        float* c4[4] = { p_hw, p_hv, p_ha, p_hg };
        int act4[4] = { 1, 0, 0, 2 };
        int nn4[4] = { 64, 64, 64, 160 };
        int cs4[4] = { BT * 64, BT * 64, BT * 64, BT * 160 };
        for (int i = 0; i < 4; ++i) {
            lora.z[i] = Z0;
            lora.z[i].Ahi = a4[i]; lora.z[i].Alo = a4[i] + BTH;
            lora.z[i].Bhi = p_ws + w4[i]; lora.z[i].Blo = p_ws + w4[i] + ws4[i];
            lora.z[i].Chi = planes(c4[i]); lora.z[i].Clo = planes(c4[i]) + cs4[i];
            lora.z[i].act = act4[i]; lora.z[i].N = nn4[i]; lora.z[i].K = 1024;
        }
        proj_all<<<2304, 256, PROJ_SMEM>>>(big, lora);
    }

    // ---- stage2 (wl,vl,al; K=64) + gB (gl; K=160) in ONE launch, per-z K
    {
        GemmBatch gbm = {};
        float* a3[3] = { p_hw, p_hv, p_ha };
        int w3[3] = { OFF_wB, OFF_vB, OFF_aB };
        float* c3[3] = { p_wl, p_vl, p_al };
        const float* b3[3] = { wb, vb, ab };
        for (int i = 0; i < 3; ++i) {
            gbm.z[i] = Z0;
            gbm.z[i].Ahi = planes(a3[i]); gbm.z[i].Alo = planes(a3[i]) + BT * 64;
            gbm.z[i].Bhi = p_ws + w3[i]; gbm.z[i].Blo = p_ws + w3[i] + SZ_LORA;
            gbm.z[i].C = c3[i]; gbm.z[i].bias = b3[i]; gbm.z[i].act = 2;
            gbm.z[i].N = 1024; gbm.z[i].K = 64;
        }
        gbm.z[3] = Z0;
        gbm.z[3].Ahi = planes(p_hg); gbm.z[3].Alo = planes(p_hg) + BT * 160;
        gbm.z[3].Bhi = p_ws + OFF_gB; gbm.z[3].Blo = p_ws + OFF_gB + SZ_G;
        gbm.z[3].C = p_gl; gbm.z[3].N = 1024; gbm.z[3].K = 160;
        gemm_mma<<<dim3(8, 64, 4), 256, G_SMEM>>>(gbm, BT);
    }

    // ---- head-layout prep (x-bufs dead -> reused)
    prep_scan_kernel<<<BT * NHh / 8, 256>>>(v_first, k_k, k_a);

    // ---- sequential scan (R13: warp-private rings, deferred o -> 4 partial planes)
    scan_kernel<<<Bb * NHh * 4, 128>>>();

    // ---- groupnorm + corr + gate (sums partials) -> y bf16 planes (g_vl, dead)
    out_stage_kernel<<<BT * NHh / 8, 256>>>(r_k, gn_w, gn_b);

    // ---- output projection
    {
        GemmBatch gbm = {};
        gbm.z[0] = Z0;
        gbm.z[0].Ahi = planes(p_vl); gbm.z[0].Alo = planes(p_vl) + BTH;
        gbm.z[0].Bhi = p_ws + OFF_WO; gbm.z[0].Blo = p_ws + OFF_WO + SZ_BIG;
        gbm.z[0].C = out; gbm.z[0].N = 1024; gbm.z[0].K = 1024;
        gemm_mma<<<dim3(8, 64, 1), 256, G_SMEM>>>(gbm, BT);
    }

    (void)in_sizes; (void)n_in; (void)out_size;
}